// round 10
// baseline (speedup 1.0000x reference)
#include <cuda_runtime.h>
#include <cuda_bf16.h>
#include <math.h>
#include <stdint.h>

// Problem dims (fixed by dataset)
constexpr int BATCH = 8192;
constexpr int DIM   = 1024;
constexpr int HID   = 256;
constexpr long long ED = (long long)BATCH * DIM;  // expert stride (floats)

// Hybrid GEMM1 tiling: rows 0-63 per CTA via mma.sync tf32 3x, rows 64-127 via f32x2 SIMT
constexpr int BM = 128;
constexpr int BN = 128;
constexpr int BK = 32;
constexpr int NT = 8192 / BK;     // 256 k-tiles
constexpr int STAGES = 2;

constexpr int AST = 36;                          // A smem stride (floats)
constexpr int A_FLOATS  = BM * AST;              // 4608
constexpr int BP_FLOATS = BK * BN;               // 4096 per plane
constexpr int STAGE_FLOATS = A_FLOATS + 3 * BP_FLOATS;   // A + Bh + Bl + Bf32
constexpr int SMEM_SZ = STAGES * STAGE_FLOATS * 4;       // 135168

// Scratch
__device__ float g_h[(size_t)BATCH * HID];                  // gelu(cat@W1+b1)
// pre-split W1: [half(2)][colblk(2)][k(8192)][n'(128)], n' XOR-swizzled by (k&3)<<3
__device__ float g_Bs[(size_t)2 * 2 * 8192 * 128];

// ---------------- helpers ----------------
__device__ __forceinline__ void splt(float x, uint32_t& h, uint32_t& l) {
    asm("cvt.rna.tf32.f32 %0, %1;" : "=r"(h) : "f"(x));
    float r = x - __uint_as_float(h);
    asm("cvt.rna.tf32.f32 %0, %1;" : "=r"(l) : "f"(r));
}
__device__ __forceinline__ float gelu_exact(float x) {
    return 0.5f * x * (1.0f + erff(x * 0.70710678118654752f));
}
__device__ __forceinline__ void cpasync16(void* dst, const void* src) {
    uint32_t d;
    asm("{ .reg .u64 t; cvta.to.shared.u64 t, %1; cvt.u32.u64 %0, t; }"
        : "=r"(d) : "l"(dst));
    asm volatile("cp.async.cg.shared.global [%0], [%1], 16;"
                 :: "r"(d), "l"(src) : "memory");
}
__device__ __forceinline__ void mma_tf32(float* c, const uint32_t* a, const uint32_t* b) {
    asm volatile(
        "mma.sync.aligned.m16n8k8.row.col.f32.tf32.tf32.f32 "
        "{%0,%1,%2,%3}, {%4,%5,%6,%7}, {%8,%9}, {%0,%1,%2,%3};"
        : "+f"(c[0]), "+f"(c[1]), "+f"(c[2]), "+f"(c[3])
        : "r"(a[0]), "r"(a[1]), "r"(a[2]), "r"(a[3]), "r"(b[0]), "r"(b[1]));
}
__device__ __forceinline__ unsigned long long pk2(float lo, float hi) {
    unsigned long long r;
    asm("mov.b64 %0, {%1,%2};" : "=l"(r)
        : "r"(__float_as_uint(lo)), "r"(__float_as_uint(hi)));
    return r;
}
__device__ __forceinline__ void ffma2(unsigned long long& d,
                                      unsigned long long a, unsigned long long b) {
    asm("fma.rn.f32x2 %0, %1, %2, %0;" : "+l"(d) : "l"(a), "l"(b));
}
__device__ __forceinline__ float2 up2(unsigned long long v) {
    unsigned int a, b;
    asm("mov.b64 {%0,%1}, %2;" : "=r"(a), "=r"(b) : "l"(v));
    return make_float2(__uint_as_float(a), __uint_as_float(b));
}

// ---------------- prep: split W1 into tf32 hi/lo planes (XOR layout) ----------------
__global__ void __launch_bounds__(256) prep_w1(const float* __restrict__ W1) {
    const int idx = blockIdx.x * 256 + threadIdx.x;   // 0 .. 2M-1
    const int n = idx & 255;
    const int k = idx >> 8;
    uint32_t h, l;
    splt(W1[idx], h, l);
    const int cb = n >> 7;
    const int nl = n & 127;
    const int np = nl ^ ((k & 3) << 3);
    const size_t base = ((size_t)cb * 8192 + k) * 128 + np;
    const size_t half = (size_t)2 * 8192 * 128;
    g_Bs[base]        = __uint_as_float(h);
    g_Bs[base + half] = __uint_as_float(l);
}

// ---------------- GEMM1 hybrid: mma(rows 0-63) + f32x2 SIMT(rows 64-127) ----------------
__global__ void __launch_bounds__(256, 1)
gemm1_hybrid(const float* __restrict__ zs, const float* __restrict__ W1,
             const float* __restrict__ b1)
{
    extern __shared__ float smem[];
    const int tid  = threadIdx.x;
    const int lane = tid & 31;
    const int wid  = tid >> 5;
    const int brow = blockIdx.y * BM;
    const int bcol = blockIdx.x * BN;
    const int cb   = blockIdx.x;

    const size_t bhalf = (size_t)2 * 8192 * 128;

    // stage layout: [A | Bh | Bl | Bf32]
    auto copy_tile = [&](int kt, int s) {
        float* As  = smem + (size_t)s * STAGE_FLOATS;
        float* Bsh = As + A_FLOATS;
        float* Bsl = Bsh + BP_FLOATS;
        float* Bsf = Bsl + BP_FLOATS;
        const int k0 = kt * BK;
        const int e  = k0 >> 10;
        const float* abase = zs + (size_t)e * ED + (k0 & 1023);
        // A: 128 rows x 32 floats = 1024 chunks
        #pragma unroll
        for (int i = 0; i < 4; i++) {
            const int c  = tid + i * 256;
            const int r  = c >> 3;
            const int kc = c & 7;
            cpasync16(As + r * AST + kc * 4,
                      abase + (size_t)(brow + r) * DIM + kc * 4);
        }
        // Bh / Bl: identity copy of pre-swizzled planes (1024 chunks each)
        const float* gb = g_Bs + ((size_t)cb * 8192 + k0) * 128;
        #pragma unroll
        for (int i = 0; i < 4; i++) {
            const int w4 = (tid + i * 256) * 4;
            cpasync16(Bsh + w4, gb + w4);
            cpasync16(Bsl + w4, gb + bhalf + w4);
        }
        // Bf32: straight copy from W1 (1024 chunks)
        #pragma unroll
        for (int i = 0; i < 4; i++) {
            const int c  = tid + i * 256;
            const int k  = c >> 5;
            const int nc = c & 31;
            cpasync16(Bsf + k * 128 + nc * 4,
                      W1 + (size_t)(k0 + k) * HID + bcol + nc * 4);
        }
        asm volatile("cp.async.commit_group;" ::: "memory");
    };

    // mma-path state (warps 0-3)
    float acc[4][4][4];
    // SIMT-path state (warps 4-7)
    unsigned long long acc2[8][4];
    if (wid < 4) {
        #pragma unroll
        for (int i = 0; i < 4; i++)
            #pragma unroll
            for (int j = 0; j < 4; j++)
                #pragma unroll
                for (int q = 0; q < 4; q++) acc[i][j][q] = 0.0f;
    } else {
        #pragma unroll
        for (int i = 0; i < 8; i++)
            #pragma unroll
            for (int j = 0; j < 4; j++) acc2[i][j] = 0ull;
    }

    copy_tile(0, 0);
    copy_tile(1, 1);

    const int l4  = lane & 3;
    const int ld4 = lane >> 2;
    const int st  = tid - 128;                 // SIMT thread id (valid when wid>=4)
    const int sr0 = 64 + ((st >> 4) << 3);     // SIMT first row (64..120)
    const int sc0 = (st & 15) << 3;            // SIMT first col (0..120)

    for (int kt = 0; kt < NT; kt++) {
        asm volatile("cp.async.wait_group 0;" ::: "memory");
        __syncthreads();

        const float* As  = smem + (size_t)(kt & 1) * STAGE_FLOATS;
        const float* Bsh = As + A_FLOATS;
        const float* Bsl = Bsh + BP_FLOATS;
        const float* Bsf = Bsl + BP_FLOATS;

        if (wid < 4) {
            // ---- tensor path: rows 0-63, warp wid owns cols wid*32..+31 ----
            const int wn = wid;
            #pragma unroll
            for (int k8 = 0; k8 < BK; k8 += 8) {
                uint32_t bh[4][2], bl[4][2];
                #pragma unroll
                for (int nt = 0; nt < 4; nt++) {
                    const int np = (wn * 32 + nt * 8 + ld4) ^ (l4 << 3);
                    const int r0 = (k8 + l4) * 128 + np;
                    bh[nt][0] = __float_as_uint(Bsh[r0]);
                    bh[nt][1] = __float_as_uint(Bsh[r0 + 4 * 128]);
                    bl[nt][0] = __float_as_uint(Bsl[r0]);
                    bl[nt][1] = __float_as_uint(Bsl[r0 + 4 * 128]);
                }
                #pragma unroll
                for (int mt = 0; mt < 4; mt++) {
                    const int m = mt * 16 + ld4;
                    uint32_t ah[4], al[4];
                    splt(As[m       * AST + k8 + l4],     ah[0], al[0]);
                    splt(As[(m + 8) * AST + k8 + l4],     ah[1], al[1]);
                    splt(As[m       * AST + k8 + l4 + 4], ah[2], al[2]);
                    splt(As[(m + 8) * AST + k8 + l4 + 4], ah[3], al[3]);
                    #pragma unroll
                    for (int nt = 0; nt < 4; nt++) {
                        mma_tf32(acc[mt][nt], ah, bh[nt]);
                        mma_tf32(acc[mt][nt], ah, bl[nt]);
                        mma_tf32(acc[mt][nt], al, bh[nt]);
                    }
                }
            }
        } else {
            // ---- fma path: rows 64-127, 8x8 per thread, packed f32x2 ----
            #pragma unroll
            for (int kk = 0; kk < BK; kk += 2) {
                float2 a2[8];
                #pragma unroll
                for (int i = 0; i < 8; i++)
                    a2[i] = *(const float2*)&As[(sr0 + i) * AST + kk];
                const float4 b0a = *(const float4*)&Bsf[kk * 128 + sc0];
                const float4 b1a = *(const float4*)&Bsf[kk * 128 + sc0 + 4];
                const float4 b0b = *(const float4*)&Bsf[(kk + 1) * 128 + sc0];
                const float4 b1b = *(const float4*)&Bsf[(kk + 1) * 128 + sc0 + 4];
                unsigned long long bpa[4], bpb[4];
                bpa[0] = pk2(b0a.x, b0a.y); bpa[1] = pk2(b0a.z, b0a.w);
                bpa[2] = pk2(b1a.x, b1a.y); bpa[3] = pk2(b1a.z, b1a.w);
                bpb[0] = pk2(b0b.x, b0b.y); bpb[1] = pk2(b0b.z, b0b.w);
                bpb[2] = pk2(b1b.x, b1b.y); bpb[3] = pk2(b1b.z, b1b.w);
                #pragma unroll
                for (int i = 0; i < 8; i++) {
                    const unsigned long long ax = pk2(a2[i].x, a2[i].x);
                    #pragma unroll
                    for (int j = 0; j < 4; j++) ffma2(acc2[i][j], ax, bpa[j]);
                    const unsigned long long ay = pk2(a2[i].y, a2[i].y);
                    #pragma unroll
                    for (int j = 0; j < 4; j++) ffma2(acc2[i][j], ay, bpb[j]);
                }
            }
        }
        __syncthreads();
        if (kt + 2 < NT) copy_tile(kt + 2, kt & 1);
    }

    // ---------------- epilogue ----------------
    if (wid < 4) {
        const int wn = wid;
        #pragma unroll
        for (int mt = 0; mt < 4; mt++) {
            const int r0 = brow + mt * 16 + ld4;
            #pragma unroll
            for (int nt = 0; nt < 4; nt++) {
                const int cg = bcol + wn * 32 + nt * 8 + 2 * l4;
                const float bx = b1[cg], by = b1[cg + 1];
                float2 o0, o1;
                o0.x = gelu_exact(acc[mt][nt][0] + bx);
                o0.y = gelu_exact(acc[mt][nt][1] + by);
                o1.x = gelu_exact(acc[mt][nt][2] + bx);
                o1.y = gelu_exact(acc[mt][nt][3] + by);
                *(float2*)(g_h + (size_t)r0 * HID + cg)       = o0;
                *(float2*)(g_h + (size_t)(r0 + 8) * HID + cg) = o1;
            }
        }
    } else {
        float bb[8];
        #pragma unroll
        for (int j = 0; j < 8; j++) bb[j] = b1[bcol + sc0 + j];
        #pragma unroll
        for (int i = 0; i < 8; i++) {
            const int rg = brow + sr0 + i;
            float4 o0, o1;
            float2 p0 = up2(acc2[i][0]);
            float2 p1 = up2(acc2[i][1]);
            float2 p2 = up2(acc2[i][2]);
            float2 p3 = up2(acc2[i][3]);
            o0.x = gelu_exact(p0.x + bb[0]);
            o0.y = gelu_exact(p0.y + bb[1]);
            o0.z = gelu_exact(p1.x + bb[2]);
            o0.w = gelu_exact(p1.y + bb[3]);
            o1.x = gelu_exact(p2.x + bb[4]);
            o1.y = gelu_exact(p2.y + bb[5]);
            o1.z = gelu_exact(p3.x + bb[6]);
            o1.w = gelu_exact(p3.y + bb[7]);
            *(float4*)(g_h + (size_t)rg * HID + bcol + sc0)     = o0;
            *(float4*)(g_h + (size_t)rg * HID + bcol + sc0 + 4) = o1;
        }
    }
}

// ---------------- gate (GEMM2 + top2 softmax) + combine ----------------
__global__ void __launch_bounds__(256, 1)
gate_combine(const float* __restrict__ W2, const float* __restrict__ b2,
             const float* __restrict__ zs,
             float* __restrict__ fused, float* __restrict__ wout)
{
    const int warp = threadIdx.x >> 5;
    const int lane = threadIdx.x & 31;
    const int row  = blockIdx.x * 8 + warp;

    const float* hrow = g_h + (size_t)row * HID;
    float acc[8] = {0.f, 0.f, 0.f, 0.f, 0.f, 0.f, 0.f, 0.f};
    #pragma unroll
    for (int kk = 0; kk < 8; kk++) {
        const int k = kk * 32 + lane;
        const float hv = hrow[k];
        const float4 wa = *(const float4*)(W2 + (size_t)k * 8);
        const float4 wb = *(const float4*)(W2 + (size_t)k * 8 + 4);
        acc[0] += hv * wa.x; acc[1] += hv * wa.y;
        acc[2] += hv * wa.z; acc[3] += hv * wa.w;
        acc[4] += hv * wb.x; acc[5] += hv * wb.y;
        acc[6] += hv * wb.z; acc[7] += hv * wb.w;
    }
    #pragma unroll
    for (int m = 0; m < 8; m++) {
        #pragma unroll
        for (int s = 16; s > 0; s >>= 1)
            acc[m] += __shfl_xor_sync(0xffffffffu, acc[m], s);
        acc[m] += b2[m];
    }

    // top-2, jax tie-break (lower index wins -> strict >)
    int i1 = 0; float l1 = acc[0];
    #pragma unroll
    for (int m = 1; m < 8; m++) if (acc[m] > l1) { l1 = acc[m]; i1 = m; }
    int i2 = (i1 == 0) ? 1 : 0; float l2 = acc[i2];
    #pragma unroll
    for (int m = 0; m < 8; m++)
        if (m != i1 && m != ((i1 == 0) ? 1 : 0) && acc[m] > l2) { l2 = acc[m]; i2 = m; }

    const float e2  = expf(l2 - l1);
    const float inv = 1.0f / (1.0f + e2);
    const float w1  = inv;
    const float w2v = e2 * inv;

    if (lane < 8)
        wout[(size_t)row * 8 + lane] =
            (lane == i1) ? w1 : ((lane == i2) ? w2v : 0.0f);

    const float4* z1 = (const float4*)(zs + (size_t)i1 * ED + (size_t)row * DIM);
    const float4* z2 = (const float4*)(zs + (size_t)i2 * ED + (size_t)row * DIM);
    float4* fo = (float4*)(fused + (size_t)row * DIM);
    #pragma unroll
    for (int v = 0; v < 8; v++) {
        const int idx = v * 32 + lane;
        const float4 A  = z1[idx];
        const float4 Bv = z2[idx];
        float4 o;
        o.x = w1 * A.x + w2v * Bv.x;
        o.y = w1 * A.y + w2v * Bv.y;
        o.z = w1 * A.z + w2v * Bv.z;
        o.w = w1 * A.w + w2v * Bv.w;
        fo[idx] = o;
    }
}

extern "C" void kernel_launch(void* const* d_in, const int* in_sizes, int n_in,
                              void* d_out, int out_size)
{
    const float* zs = (const float*)d_in[0];
    const float* W1 = (const float*)d_in[1];
    const float* b1 = (const float*)d_in[2];
    const float* W2 = (const float*)d_in[3];
    const float* b2 = (const float*)d_in[4];

    float* out   = (float*)d_out;
    float* fused = out;                        // [B, D]
    float* wout  = out + (size_t)BATCH * DIM;  // [B, M]

    cudaFuncSetAttribute(gemm1_hybrid, cudaFuncAttributeMaxDynamicSharedMemorySize, SMEM_SZ);

    prep_w1<<<(8192 * 256) / 256, 256>>>(W1);
    gemm1_hybrid<<<dim3(HID / BN, BATCH / BM), 256, SMEM_SZ>>>(zs, W1, b1);
    gate_combine<<<BATCH / 8, 256>>>(W2, b2, zs, fused, wout);
}

// round 11
// speedup vs baseline: 1.6084x; 1.6084x over previous
#include <cuda_runtime.h>
#include <cuda_bf16.h>
#include <math.h>
#include <stdint.h>

// Problem dims (fixed by dataset)
constexpr int BATCH = 8192;
constexpr int DIM   = 1024;
constexpr int HID   = 256;
constexpr long long ED = (long long)BATCH * DIM;  // expert stride (floats)

// GEMM1 tiling: mixed tf32-main + bf16-cross emulation
constexpr int BM = 128;
constexpr int BN = 128;
constexpr int BK = 32;
constexpr int NT = 8192 / BK;     // 256 k-tiles
constexpr int STAGES = 3;

constexpr int AST = 36;                       // A smem stride (floats), conflict-free 32b frags
constexpr int A_FLOATS   = BM * AST;          // 4608
constexpr int BH_FLOATS  = BK * 136;          // 4352 (tf32 plane, stride 136)
constexpr int BF_U32     = 2 * 16 * 136;      // 4352 (bl + bb bf16x2 planes, stride 136)
constexpr int STAGE_FLOATS = A_FLOATS + BH_FLOATS + BF_U32;  // 13312
constexpr int SMEM_SZ = STAGES * STAGE_FLOATS * 4;           // 159744

// Scratch
__device__ float g_h[(size_t)BATCH * HID];                    // gelu(cat@W1+b1)
// Pre-converted W1 images, ready for identity cp.async:
// g_Bh : [cb(2)][ktile(256)][32][136]  fp32 (tf32-valued)
__device__ float    g_Bh[(size_t)2 * 256 * 4352];
// g_Bbf: [cb(2)][ktile(256)][ bl[16][136] | bb[16][136] ]  bf16x2
__device__ uint32_t g_Bbf[(size_t)2 * 256 * 4352];

// ---------------- helpers ----------------
__device__ __forceinline__ uint32_t tf32_of(float x) {
    uint32_t h;
    asm("cvt.rna.tf32.f32 %0, %1;" : "=r"(h) : "f"(x));
    return h;
}
// pack {hi, lo} -> bf16x2 (lo = k-even element)
__device__ __forceinline__ uint32_t bf2(float lo, float hi) {
    uint32_t r;
    asm("cvt.rn.bf16x2.f32 %0, %1, %2;" : "=r"(r) : "f"(hi), "f"(lo));
    return r;
}
__device__ __forceinline__ float gelu_exact(float x) {
    return 0.5f * x * (1.0f + erff(x * 0.70710678118654752f));
}
__device__ __forceinline__ void cpasync16(void* dst, const void* src) {
    uint32_t d;
    asm("{ .reg .u64 t; cvta.to.shared.u64 t, %1; cvt.u32.u64 %0, t; }"
        : "=r"(d) : "l"(dst));
    asm volatile("cp.async.cg.shared.global [%0], [%1], 16;"
                 :: "r"(d), "l"(src) : "memory");
}
__device__ __forceinline__ void mma_tf32(float* c, const uint32_t* a, const uint32_t* b) {
    asm volatile(
        "mma.sync.aligned.m16n8k8.row.col.f32.tf32.tf32.f32 "
        "{%0,%1,%2,%3}, {%4,%5,%6,%7}, {%8,%9}, {%0,%1,%2,%3};"
        : "+f"(c[0]), "+f"(c[1]), "+f"(c[2]), "+f"(c[3])
        : "r"(a[0]), "r"(a[1]), "r"(a[2]), "r"(a[3]), "r"(b[0]), "r"(b[1]));
}
__device__ __forceinline__ void mma_bf16(float* c, const uint32_t* a, const uint32_t* b) {
    asm volatile(
        "mma.sync.aligned.m16n8k16.row.col.f32.bf16.bf16.f32 "
        "{%0,%1,%2,%3}, {%4,%5,%6,%7}, {%8,%9}, {%0,%1,%2,%3};"
        : "+f"(c[0]), "+f"(c[1]), "+f"(c[2]), "+f"(c[3])
        : "r"(a[0]), "r"(a[1]), "r"(a[2]), "r"(a[3]), "r"(b[0]), "r"(b[1]));
}

// ---------------- prep: W1 -> tf32 plane + bf16 cross planes ----------------
// one thread per (k-pair, n): 4096 x 256 = 1M threads
__global__ void __launch_bounds__(256) prep_w1(const float* __restrict__ W1) {
    const int idx = blockIdx.x * 256 + threadIdx.x;
    const int n  = idx & 255;
    const int k2 = idx >> 8;             // 0..4095
    const float x0 = W1[(size_t)(2 * k2)     * HID + n];
    const float x1 = W1[(size_t)(2 * k2 + 1) * HID + n];
    const int cb  = n >> 7;
    const int nl  = n & 127;
    const int kt  = k2 >> 4;
    const int row = k2 & 15;             // bf16 plane row (k-pair)
    const int kr  = row << 1;            // tf32 plane rows

    const float h0 = __uint_as_float(tf32_of(x0));
    const float h1 = __uint_as_float(tf32_of(x1));
    float* bh = g_Bh + ((size_t)cb * 256 + kt) * 4352;
    bh[kr * 136 + nl]       = h0;
    bh[(kr + 1) * 136 + nl] = h1;

    uint32_t* bf = g_Bbf + ((size_t)cb * 256 + kt) * 4352;
    bf[row * 136 + nl]        = bf2(x0 - h0, x1 - h1);   // Bl plane
    bf[2176 + row * 136 + nl] = bf2(x0, x1);             // Bb plane
}

// ---------------- GEMM1: tf32 main + bf16 cross + bias + GELU ----------------
__global__ void __launch_bounds__(256, 1)
gemm1_mix(const float* __restrict__ zs, const float* __restrict__ b1)
{
    extern __shared__ float smem[];
    const int tid  = threadIdx.x;
    const int lane = tid & 31;
    const int wid  = tid >> 5;
    const int wm   = wid & 1;          // 2 warps along M (64 each)
    const int wn   = wid >> 1;         // 4 warps along N (32 each)
    const int brow = blockIdx.y * BM;
    const int bcol = blockIdx.x * BN;
    const int cb   = blockIdx.x;

    auto copy_tile = [&](int kt, int s) {
        float*    As = smem + (size_t)s * STAGE_FLOATS;
        float*    Bh = As + A_FLOATS;
        uint32_t* Bf = (uint32_t*)(Bh + BH_FLOATS);
        const int k0 = kt * BK;
        const int e  = k0 >> 10;
        const float* abase = zs + (size_t)e * ED + (k0 & 1023);
        // A: 128 rows x 32 floats = 1024 chunks (4 per thread)
        #pragma unroll
        for (int i = 0; i < 4; i++) {
            const int c  = tid + i * 256;
            const int r  = c >> 3;
            const int kc = c & 7;
            cpasync16(As + r * AST + kc * 4,
                      abase + (size_t)(brow + r) * DIM + kc * 4);
        }
        // Bh / Bbf: identity copies of padded images (1088 chunks each)
        const float*    gbh = g_Bh  + ((size_t)cb * 256 + kt) * 4352;
        const uint32_t* gbf = g_Bbf + ((size_t)cb * 256 + kt) * 4352;
        #pragma unroll
        for (int i = 0; i < 5; i++) {
            const int c = tid + i * 256;
            if (c < 1088) {
                cpasync16(Bh + c * 4, gbh + c * 4);
                cpasync16(Bf + c * 4, gbf + c * 4);
            }
        }
        asm volatile("cp.async.commit_group;" ::: "memory");
    };

    float acc[4][4][4];
    #pragma unroll
    for (int i = 0; i < 4; i++)
        #pragma unroll
        for (int j = 0; j < 4; j++)
            #pragma unroll
            for (int q = 0; q < 4; q++) acc[i][j][q] = 0.0f;

    copy_tile(0, 0);
    copy_tile(1, 1);

    const int l4  = lane & 3;
    const int ld4 = lane >> 2;

    for (int kt = 0; kt < NT; kt++) {
        asm volatile("cp.async.wait_group %0;" :: "n"(STAGES - 2) : "memory");
        __syncthreads();
        if (kt + STAGES - 1 < NT)
            copy_tile(kt + STAGES - 1, (kt + STAGES - 1) % STAGES);
        else
            asm volatile("cp.async.commit_group;" ::: "memory");

        const float*    As = smem + (size_t)(kt % STAGES) * STAGE_FLOATS;
        const float*    Bh = As + A_FLOATS;
        const uint32_t* Bf = (const uint32_t*)(Bh + BH_FLOATS);

        // ---- tf32 main term: 4 k8 steps ----
        #pragma unroll
        for (int k8 = 0; k8 < BK; k8 += 8) {
            uint32_t bT[4][2];
            #pragma unroll
            for (int nt = 0; nt < 4; nt++) {
                const int n = wn * 32 + nt * 8 + ld4;
                bT[nt][0] = __float_as_uint(Bh[(k8 + l4)     * 136 + n]);
                bT[nt][1] = __float_as_uint(Bh[(k8 + l4 + 4) * 136 + n]);
            }
            #pragma unroll
            for (int mt = 0; mt < 4; mt++) {
                const int m = wm * 64 + mt * 16 + ld4;
                uint32_t ah[4];
                ah[0] = tf32_of(As[m       * AST + k8 + l4]);
                ah[1] = tf32_of(As[(m + 8) * AST + k8 + l4]);
                ah[2] = tf32_of(As[m       * AST + k8 + l4 + 4]);
                ah[3] = tf32_of(As[(m + 8) * AST + k8 + l4 + 4]);
                #pragma unroll
                for (int nt = 0; nt < 4; nt++)
                    mma_tf32(acc[mt][nt], ah, bT[nt]);
            }
        }

        // ---- bf16 cross terms: 2 k16 steps ----
        #pragma unroll
        for (int s = 0; s < 2; s++) {
            uint32_t bL[4][2], bB[4][2];
            #pragma unroll
            for (int nt = 0; nt < 4; nt++) {
                const int n  = wn * 32 + nt * 8 + ld4;
                const int r0 = s * 8 + l4;
                bL[nt][0] = Bf[r0 * 136 + n];
                bL[nt][1] = Bf[(r0 + 4) * 136 + n];
                bB[nt][0] = Bf[2176 + r0 * 136 + n];
                bB[nt][1] = Bf[2176 + (r0 + 4) * 136 + n];
            }
            #pragma unroll
            for (int mt = 0; mt < 4; mt++) {
                const int m  = wm * 64 + mt * 16 + ld4;
                const int kk = s * 16 + 2 * l4;
                const float2 xa = *(const float2*)&As[m       * AST + kk];
                const float2 xb = *(const float2*)&As[(m + 8) * AST + kk];
                const float2 xc = *(const float2*)&As[m       * AST + kk + 8];
                const float2 xd = *(const float2*)&As[(m + 8) * AST + kk + 8];
                uint32_t ab[4], al[4];
                ab[0] = bf2(xa.x, xa.y);
                ab[1] = bf2(xb.x, xb.y);
                ab[2] = bf2(xc.x, xc.y);
                ab[3] = bf2(xd.x, xd.y);
                {
                    const float ha0 = __uint_as_float(tf32_of(xa.x));
                    const float ha1 = __uint_as_float(tf32_of(xa.y));
                    const float hb0 = __uint_as_float(tf32_of(xb.x));
                    const float hb1 = __uint_as_float(tf32_of(xb.y));
                    const float hc0 = __uint_as_float(tf32_of(xc.x));
                    const float hc1 = __uint_as_float(tf32_of(xc.y));
                    const float hd0 = __uint_as_float(tf32_of(xd.x));
                    const float hd1 = __uint_as_float(tf32_of(xd.y));
                    al[0] = bf2(xa.x - ha0, xa.y - ha1);
                    al[1] = bf2(xb.x - hb0, xb.y - hb1);
                    al[2] = bf2(xc.x - hc0, xc.y - hc1);
                    al[3] = bf2(xd.x - hd0, xd.y - hd1);
                }
                #pragma unroll
                for (int nt = 0; nt < 4; nt++) {
                    mma_bf16(acc[mt][nt], ab, bL[nt]);   // bf16(A) * Bl
                    mma_bf16(acc[mt][nt], al, bB[nt]);   // Al * bf16(B)
                }
            }
        }
    }

    // epilogue: bias + exact GELU, direct STG
    #pragma unroll
    for (int mt = 0; mt < 4; mt++) {
        const int r0 = brow + wm * 64 + mt * 16 + ld4;
        #pragma unroll
        for (int nt = 0; nt < 4; nt++) {
            const int cg = bcol + wn * 32 + nt * 8 + 2 * l4;
            const float bx = b1[cg], by = b1[cg + 1];
            float2 o0, o1;
            o0.x = gelu_exact(acc[mt][nt][0] + bx);
            o0.y = gelu_exact(acc[mt][nt][1] + by);
            o1.x = gelu_exact(acc[mt][nt][2] + bx);
            o1.y = gelu_exact(acc[mt][nt][3] + by);
            *(float2*)(g_h + (size_t)r0 * HID + cg)       = o0;
            *(float2*)(g_h + (size_t)(r0 + 8) * HID + cg) = o1;
        }
    }
}

// ---------------- gate (GEMM2 + top2 softmax) + combine ----------------
__global__ void __launch_bounds__(256, 1)
gate_combine(const float* __restrict__ W2, const float* __restrict__ b2,
             const float* __restrict__ zs,
             float* __restrict__ fused, float* __restrict__ wout)
{
    const int warp = threadIdx.x >> 5;
    const int lane = threadIdx.x & 31;
    const int row  = blockIdx.x * 8 + warp;

    const float* hrow = g_h + (size_t)row * HID;
    float acc[8] = {0.f, 0.f, 0.f, 0.f, 0.f, 0.f, 0.f, 0.f};
    #pragma unroll
    for (int kk = 0; kk < 8; kk++) {
        const int k = kk * 32 + lane;
        const float hv = hrow[k];
        const float4 wa = *(const float4*)(W2 + (size_t)k * 8);
        const float4 wb = *(const float4*)(W2 + (size_t)k * 8 + 4);
        acc[0] += hv * wa.x; acc[1] += hv * wa.y;
        acc[2] += hv * wa.z; acc[3] += hv * wa.w;
        acc[4] += hv * wb.x; acc[5] += hv * wb.y;
        acc[6] += hv * wb.z; acc[7] += hv * wb.w;
    }
    #pragma unroll
    for (int m = 0; m < 8; m++) {
        #pragma unroll
        for (int s = 16; s > 0; s >>= 1)
            acc[m] += __shfl_xor_sync(0xffffffffu, acc[m], s);
        acc[m] += b2[m];
    }

    // top-2, jax tie-break (lower index wins -> strict >)
    int i1 = 0; float l1 = acc[0];
    #pragma unroll
    for (int m = 1; m < 8; m++) if (acc[m] > l1) { l1 = acc[m]; i1 = m; }
    int i2 = (i1 == 0) ? 1 : 0; float l2 = acc[i2];
    #pragma unroll
    for (int m = 0; m < 8; m++)
        if (m != i1 && m != ((i1 == 0) ? 1 : 0) && acc[m] > l2) { l2 = acc[m]; i2 = m; }

    const float e2  = expf(l2 - l1);
    const float inv = 1.0f / (1.0f + e2);
    const float w1  = inv;
    const float w2v = e2 * inv;

    if (lane < 8)
        wout[(size_t)row * 8 + lane] =
            (lane == i1) ? w1 : ((lane == i2) ? w2v : 0.0f);

    const float4* z1 = (const float4*)(zs + (size_t)i1 * ED + (size_t)row * DIM);
    const float4* z2 = (const float4*)(zs + (size_t)i2 * ED + (size_t)row * DIM);
    float4* fo = (float4*)(fused + (size_t)row * DIM);
    #pragma unroll
    for (int v = 0; v < 8; v++) {
        const int idx = v * 32 + lane;
        const float4 A  = z1[idx];
        const float4 Bv = z2[idx];
        float4 o;
        o.x = w1 * A.x + w2v * Bv.x;
        o.y = w1 * A.y + w2v * Bv.y;
        o.z = w1 * A.z + w2v * Bv.z;
        o.w = w1 * A.w + w2v * Bv.w;
        fo[idx] = o;
    }
}

extern "C" void kernel_launch(void* const* d_in, const int* in_sizes, int n_in,
                              void* d_out, int out_size)
{
    const float* zs = (const float*)d_in[0];
    const float* W1 = (const float*)d_in[1];
    const float* b1 = (const float*)d_in[2];
    const float* W2 = (const float*)d_in[3];
    const float* b2 = (const float*)d_in[4];

    float* out   = (float*)d_out;
    float* fused = out;                        // [B, D]
    float* wout  = out + (size_t)BATCH * DIM;  // [B, M]

    cudaFuncSetAttribute(gemm1_mix, cudaFuncAttributeMaxDynamicSharedMemorySize, SMEM_SZ);

    prep_w1<<<(4096 * 256) / 256, 256>>>(W1);
    gemm1_mix<<<dim3(HID / BN, BATCH / BM), 256, SMEM_SZ>>>(zs, b1);
    gate_combine<<<BATCH / 8, 256>>>(W2, b2, zs, fused, wout);
}

// round 13
// speedup vs baseline: 2.2929x; 1.4256x over previous
#include <cuda_runtime.h>
#include <cuda_fp16.h>
#include <math.h>
#include <stdint.h>

// Problem dims (fixed by dataset)
constexpr int BATCH = 8192;
constexpr int DIM   = 1024;
constexpr int HID   = 256;
constexpr long long ED = (long long)BATCH * DIM;  // expert stride (floats)

// GEMM1 tiling: fp16 Markidis 3-term emulation (all mma m16n8k16.f16, f32 accum)
constexpr int BM = 128;
constexpr int BN = 128;
constexpr int BK = 32;
constexpr int NT = 8192 / BK;     // 256 k-tiles
constexpr int STAGES = 3;

constexpr float LO_SCALE   = 16384.0f;          // 2^14 (keeps B residuals normal in fp16)
constexpr float LO_DESCALE = 1.0f / 16384.0f;

constexpr int AST = 36;                       // A smem stride (floats), conflict-free frags
constexpr int A_FLOATS = BM * AST;            // 4608
constexpr int BF_U32   = 2 * 16 * 136;        // 4352: hi[16][136] | lo[16][136] (half2)
constexpr int STAGE_FLOATS = A_FLOATS + BF_U32;        // 8960
constexpr int SMEM_SZ = STAGES * STAGE_FLOATS * 4;     // 107520

// Scratch
__device__ float g_h[(size_t)BATCH * HID];                 // gelu(cat@W1+b1)
// pre-converted W1: [cb(2)][ktile(256)][ hi[16][136] | lo*2^14 [16][136] ] half2
__device__ uint32_t g_Bf16[(size_t)2 * 256 * 4352];

// ---------------- helpers ----------------
// pack {lo (k-even), hi (k-odd)} -> f16x2; first PTX src lands in HIGH half
__device__ __forceinline__ uint32_t h2pk(float lo, float hi) {
    uint32_t r;
    asm("cvt.rn.f16x2.f32 %0, %1, %2;" : "=r"(r) : "f"(hi), "f"(lo));
    return r;
}
__device__ __forceinline__ float2 h2up(uint32_t v) {
    float lo, hi;
    asm("{ .reg .f16 l, h; mov.b32 {l, h}, %2;\n\t"
        "  cvt.f32.f16 %0, l; cvt.f32.f16 %1, h; }"
        : "=f"(lo), "=f"(hi) : "r"(v));
    return make_float2(lo, hi);
}
__device__ __forceinline__ float gelu_exact(float x) {
    return 0.5f * x * (1.0f + erff(x * 0.70710678118654752f));
}
__device__ __forceinline__ void cpasync16(void* dst, const void* src) {
    uint32_t d;
    asm("{ .reg .u64 t; cvta.to.shared.u64 t, %1; cvt.u32.u64 %0, t; }"
        : "=r"(d) : "l"(dst));
    asm volatile("cp.async.cg.shared.global [%0], [%1], 16;"
                 :: "r"(d), "l"(src) : "memory");
}
__device__ __forceinline__ void mma_f16(float* c, const uint32_t* a, const uint32_t* b) {
    asm volatile(
        "mma.sync.aligned.m16n8k16.row.col.f32.f16.f16.f32 "
        "{%0,%1,%2,%3}, {%4,%5,%6,%7}, {%8,%9}, {%0,%1,%2,%3};"
        : "+f"(c[0]), "+f"(c[1]), "+f"(c[2]), "+f"(c[3])
        : "r"(a[0]), "r"(a[1]), "r"(a[2]), "r"(a[3]), "r"(b[0]), "r"(b[1]));
}

// ---------------- prep: W1 -> fp16 hi plane + scaled fp16 residual plane ----------------
// one thread per (k-pair, n): 4096 x 256
__global__ void __launch_bounds__(256) prep_w1(const float* __restrict__ W1) {
    const int idx = blockIdx.x * 256 + threadIdx.x;
    const int n  = idx & 255;
    const int k2 = idx >> 8;             // 0..4095
    const float x0 = W1[(size_t)(2 * k2)     * HID + n];
    const float x1 = W1[(size_t)(2 * k2 + 1) * HID + n];
    const int cb  = n >> 7;
    const int nl  = n & 127;
    const int kt  = k2 >> 4;
    const int row = k2 & 15;             // k-pair row within tile

    const uint32_t h = h2pk(x0, x1);
    const float2 hf = h2up(h);
    const uint32_t l = h2pk((x0 - hf.x) * LO_SCALE, (x1 - hf.y) * LO_SCALE);

    uint32_t* bf = g_Bf16 + ((size_t)cb * 256 + kt) * 4352;
    bf[row * 136 + nl]        = h;
    bf[2176 + row * 136 + nl] = l;
}

// ---------------- GEMM1: fp16 3-term + bias + GELU ----------------
__global__ void __launch_bounds__(256, 1)
gemm1_f16(const float* __restrict__ zs, const float* __restrict__ b1)
{
    extern __shared__ float smem[];
    const int tid  = threadIdx.x;
    const int lane = tid & 31;
    const int wid  = tid >> 5;
    const int wm   = wid & 1;          // 2 warps along M (64 each)
    const int wn   = wid >> 1;         // 4 warps along N (32 each)
    const int brow = blockIdx.y * BM;
    const int bcol = blockIdx.x * BN;
    const int cb   = blockIdx.x;

    auto copy_tile = [&](int kt, int s) {
        float*    As = smem + (size_t)s * STAGE_FLOATS;
        uint32_t* Bf = (uint32_t*)(As + A_FLOATS);
        const int k0 = kt * BK;
        const int e  = k0 >> 10;
        const float* abase = zs + (size_t)e * ED + (k0 & 1023);
        // A: 128 rows x 32 floats = 1024 chunks (4 per thread)
        #pragma unroll
        for (int i = 0; i < 4; i++) {
            const int c  = tid + i * 256;
            const int r  = c >> 3;
            const int kc = c & 7;
            cpasync16(As + r * AST + kc * 4,
                      abase + (size_t)(brow + r) * DIM + kc * 4);
        }
        // B: identity copy of padded half2 planes (1088 chunks)
        const uint32_t* gbf = g_Bf16 + ((size_t)cb * 256 + kt) * 4352;
        #pragma unroll
        for (int i = 0; i < 5; i++) {
            const int c = tid + i * 256;
            if (c < 1088) cpasync16(Bf + c * 4, gbf + c * 4);
        }
        asm volatile("cp.async.commit_group;" ::: "memory");
    };

    float accA[4][4][4];   // Ah*Bh + Al*Bh  (unscaled)
    float accB[4][4][4];   // Ah*Bl'         (scale 2^14)
    #pragma unroll
    for (int i = 0; i < 4; i++)
        #pragma unroll
        for (int j = 0; j < 4; j++)
            #pragma unroll
            for (int q = 0; q < 4; q++) { accA[i][j][q] = 0.0f; accB[i][j][q] = 0.0f; }

    copy_tile(0, 0);
    copy_tile(1, 1);

    const int l4  = lane & 3;
    const int ld4 = lane >> 2;

    for (int kt = 0; kt < NT; kt++) {
        asm volatile("cp.async.wait_group %0;" :: "n"(STAGES - 2) : "memory");
        __syncthreads();
        if (kt + STAGES - 1 < NT)
            copy_tile(kt + STAGES - 1, (kt + STAGES - 1) % STAGES);
        else
            asm volatile("cp.async.commit_group;" ::: "memory");

        const float*    As = smem + (size_t)(kt % STAGES) * STAGE_FLOATS;
        const uint32_t* Bf = (const uint32_t*)(As + A_FLOATS);

        #pragma unroll
        for (int s = 0; s < 2; s++) {
            // B fragments for this k16 step
            uint32_t bH[4][2], bL[4][2];
            #pragma unroll
            for (int nt = 0; nt < 4; nt++) {
                const int n  = wn * 32 + nt * 8 + ld4;
                const int r0 = s * 8 + l4;
                bH[nt][0] = Bf[r0 * 136 + n];
                bH[nt][1] = Bf[(r0 + 4) * 136 + n];
                bL[nt][0] = Bf[2176 + r0 * 136 + n];
                bL[nt][1] = Bf[2176 + (r0 + 4) * 136 + n];
            }
            #pragma unroll
            for (int mt = 0; mt < 4; mt++) {
                const int m  = wm * 64 + mt * 16 + ld4;
                const int kk = s * 16 + 2 * l4;
                const float2 xa = *(const float2*)&As[m       * AST + kk];
                const float2 xb = *(const float2*)&As[(m + 8) * AST + kk];
                const float2 xc = *(const float2*)&As[m       * AST + kk + 8];
                const float2 xd = *(const float2*)&As[(m + 8) * AST + kk + 8];
                uint32_t ah[4], al[4];
                ah[0] = h2pk(xa.x, xa.y);
                ah[1] = h2pk(xb.x, xb.y);
                ah[2] = h2pk(xc.x, xc.y);
                ah[3] = h2pk(xd.x, xd.y);
                {
                    const float2 fa = h2up(ah[0]);
                    const float2 fb = h2up(ah[1]);
                    const float2 fc = h2up(ah[2]);
                    const float2 fd = h2up(ah[3]);
                    al[0] = h2pk(xa.x - fa.x, xa.y - fa.y);
                    al[1] = h2pk(xb.x - fb.x, xb.y - fb.y);
                    al[2] = h2pk(xc.x - fc.x, xc.y - fc.y);
                    al[3] = h2pk(xd.x - fd.x, xd.y - fd.y);
                }
                #pragma unroll
                for (int nt = 0; nt < 4; nt++) {
                    mma_f16(accA[mt][nt], ah, bH[nt]);   // main: Ah*Bh
                    mma_f16(accA[mt][nt], al, bH[nt]);   // cross: Al*Bh
                    mma_f16(accB[mt][nt], ah, bL[nt]);   // cross: Ah*Bl' (scaled)
                }
            }
        }
    }

    // epilogue: merge scaled accumulator, bias + exact GELU, direct STG
    #pragma unroll
    for (int mt = 0; mt < 4; mt++) {
        const int r0 = brow + wm * 64 + mt * 16 + ld4;
        #pragma unroll
        for (int nt = 0; nt < 4; nt++) {
            const int cg = bcol + wn * 32 + nt * 8 + 2 * l4;
            const float bx = b1[cg], by = b1[cg + 1];
            float v0 = accA[mt][nt][0] + accB[mt][nt][0] * LO_DESCALE + bx;
            float v1 = accA[mt][nt][1] + accB[mt][nt][1] * LO_DESCALE + by;
            float v2 = accA[mt][nt][2] + accB[mt][nt][2] * LO_DESCALE + bx;
            float v3 = accA[mt][nt][3] + accB[mt][nt][3] * LO_DESCALE + by;
            float2 o0, o1;
            o0.x = gelu_exact(v0);
            o0.y = gelu_exact(v1);
            o1.x = gelu_exact(v2);
            o1.y = gelu_exact(v3);
            *(float2*)(g_h + (size_t)r0 * HID + cg)       = o0;
            *(float2*)(g_h + (size_t)(r0 + 8) * HID + cg) = o1;
        }
    }
}

// ---------------- gate (GEMM2 + top2 softmax) + combine ----------------
__global__ void __launch_bounds__(256, 1)
gate_combine(const float* __restrict__ W2, const float* __restrict__ b2,
             const float* __restrict__ zs,
             float* __restrict__ fused, float* __restrict__ wout)
{
    const int warp = threadIdx.x >> 5;
    const int lane = threadIdx.x & 31;
    const int row  = blockIdx.x * 8 + warp;

    const float* hrow = g_h + (size_t)row * HID;
    float acc[8] = {0.f, 0.f, 0.f, 0.f, 0.f, 0.f, 0.f, 0.f};
    #pragma unroll
    for (int kk = 0; kk < 8; kk++) {
        const int k = kk * 32 + lane;
        const float hv = hrow[k];
        const float4 wa = *(const float4*)(W2 + (size_t)k * 8);
        const float4 wb = *(const float4*)(W2 + (size_t)k * 8 + 4);
        acc[0] += hv * wa.x; acc[1] += hv * wa.y;
        acc[2] += hv * wa.z; acc[3] += hv * wa.w;
        acc[4] += hv * wb.x; acc[5] += hv * wb.y;
        acc[6] += hv * wb.z; acc[7] += hv * wb.w;
    }
    #pragma unroll
    for (int m = 0; m < 8; m++) {
        #pragma unroll
        for (int s = 16; s > 0; s >>= 1)
            acc[m] += __shfl_xor_sync(0xffffffffu, acc[m], s);
        acc[m] += b2[m];
    }

    // top-2, jax tie-break (lower index wins -> strict >)
    int i1 = 0; float l1 = acc[0];
    #pragma unroll
    for (int m = 1; m < 8; m++) if (acc[m] > l1) { l1 = acc[m]; i1 = m; }
    int i2 = (i1 == 0) ? 1 : 0; float l2 = acc[i2];
    #pragma unroll
    for (int m = 0; m < 8; m++)
        if (m != i1 && m != ((i1 == 0) ? 1 : 0) && acc[m] > l2) { l2 = acc[m]; i2 = m; }

    const float e2  = expf(l2 - l1);
    const float inv = 1.0f / (1.0f + e2);
    const float w1  = inv;
    const float w2v = e2 * inv;

    if (lane < 8)
        wout[(size_t)row * 8 + lane] =
            (lane == i1) ? w1 : ((lane == i2) ? w2v : 0.0f);

    const float4* z1 = (const float4*)(zs + (size_t)i1 * ED + (size_t)row * DIM);
    const float4* z2 = (const float4*)(zs + (size_t)i2 * ED + (size_t)row * DIM);
    float4* fo = (float4*)(fused + (size_t)row * DIM);
    #pragma unroll
    for (int v = 0; v < 8; v++) {
        const int idx = v * 32 + lane;
        const float4 A  = z1[idx];
        const float4 Bv = z2[idx];
        float4 o;
        o.x = w1 * A.x + w2v * Bv.x;
        o.y = w1 * A.y + w2v * Bv.y;
        o.z = w1 * A.z + w2v * Bv.z;
        o.w = w1 * A.w + w2v * Bv.w;
        fo[idx] = o;
    }
}

extern "C" void kernel_launch(void* const* d_in, const int* in_sizes, int n_in,
                              void* d_out, int out_size)
{
    const float* zs = (const float*)d_in[0];
    const float* W1 = (const float*)d_in[1];
    const float* b1 = (const float*)d_in[2];
    const float* W2 = (const float*)d_in[3];
    const float* b2 = (const float*)d_in[4];

    float* out   = (float*)d_out;
    float* fused = out;                        // [B, D]
    float* wout  = out + (size_t)BATCH * DIM;  // [B, M]

    cudaFuncSetAttribute(gemm1_f16, cudaFuncAttributeMaxDynamicSharedMemorySize, SMEM_SZ);

    prep_w1<<<(4096 * 256) / 256, 256>>>(W1);
    gemm1_f16<<<dim3(HID / BN, BATCH / BM), 256, SMEM_SZ>>>(zs, b1);
    gate_combine<<<BATCH / 8, 256>>>(W2, b2, zs, fused, wout);
}